// round 14
// baseline (speedup 1.0000x reference)
#include <cuda_runtime.h>
#include <cuda_bf16.h>
#include <cstdint>

#define BATCH 2
#define SEQ   2048
#define SA    2051
#define HID   1024
#define NH    16
#define HD    64
#define SEQSTR ((size_t)BATCH * SA * HID)
#define MROWS  (2 * BATCH * SA)          // 8204 rows (both seqs)

// ---------------- scratch ----------------------------------------------------
__device__ float g_aug [2 * BATCH * SA * HID];
__device__ float g_q   [2 * BATCH * NH * SA * HD];
__device__ float g_k   [2 * BATCH * NH * SA * HD];
__device__ float g_v   [2 * BATCH * NH * SA * HD];
__device__ float g_att [2 * BATCH * SA * HID];
__device__ float g_proj[2 * BATCH * SA * HID];

// ---------------- helpers ----------------------------------------------------
__device__ __forceinline__ void mma_tf32(float* c, const uint32_t* a, const uint32_t* b) {
    asm volatile(
        "mma.sync.aligned.m16n8k8.row.col.f32.tf32.tf32.f32 "
        "{%0,%1,%2,%3}, {%4,%5,%6,%7}, {%8,%9}, {%0,%1,%2,%3};"
        : "+f"(c[0]), "+f"(c[1]), "+f"(c[2]), "+f"(c[3])
        : "r"(a[0]), "r"(a[1]), "r"(a[2]), "r"(a[3]), "r"(b[0]), "r"(b[1]));
}

__device__ __forceinline__ uint32_t smaddr(const void* p) {
    return (uint32_t)__cvta_generic_to_shared(p);
}
#define CPA16(dst, src, sz) \
    asm volatile("cp.async.cg.shared.global [%0], [%1], 16, %2;" :: "r"(dst), "l"(src), "r"(sz))
#define CPA_COMMIT() asm volatile("cp.async.commit_group;")
#define CPA_WAIT0()  asm volatile("cp.async.wait_group 0;" ::: "memory")

__device__ __forceinline__ uint32_t fu(float x) { return __float_as_uint(x); }

// ---------------- build augmented sequences ----------------------------------
__global__ void build_aug_kernel(const float* __restrict__ cnn,
                                 const float* __restrict__ llm,
                                 const float* __restrict__ ee,
                                 const float* __restrict__ me,
                                 const float* __restrict__ pe,
                                 float* __restrict__ aug)
{
    int s = blockIdx.x, b = blockIdx.y, seq = blockIdx.z;
    const float* src;
    if (s < SEQ) src = (seq == 0 ? cnn : llm) + ((size_t)b * SEQ + s) * HID;
    else         src = (s == SEQ ? ee : (s == SEQ + 1 ? me : pe));
    float* dst = aug + (((size_t)seq * BATCH + b) * SA + s) * HID;
    int j = threadIdx.x * 4;
    float4 v = *(const float4*)(src + j);
    *(float4*)(dst + j) = v;
}

// ---------------- TF32 GEMM with cp.async pipeline ---------------------------
// X [M,1024] row-major, W [1024,1024] row-major. BM=BN=128, BK=16, 256 thr.
// 8 warps: 4(m) x 2(n), warp tile 32x64. blockIdx.z selects (W,bias,Y).
// Raw fp32 bits fed to tf32 mma (hardware ignores low mantissa bits).
template<int OUT_HEADMAJOR>
__global__ __launch_bounds__(256) void sgemm_tf32(
    const float* __restrict__ X,
    const float* __restrict__ W0, const float* __restrict__ W1, const float* __restrict__ W2,
    const float* __restrict__ bias0, const float* __restrict__ bias1, const float* __restrict__ bias2,
    float* __restrict__ Y0, float* __restrict__ Y1, float* __restrict__ Y2,
    int M)
{
    __shared__ __align__(16) float As[2][128][20];   // [m][k], stride 20: banks 20g+t all distinct
    __shared__ __align__(16) float Bs[2][16][136];   // [k][n], stride 136: banks 8t+g all distinct

    const int K = 1024;
    int z = blockIdx.z;
    const float* W    = (z == 0) ? W0 : (z == 1) ? W1 : W2;
    const float* bias = (z == 0) ? bias0 : (z == 1) ? bias1 : bias2;
    float*       Y    = (z == 0) ? Y0 : (z == 1) ? Y1 : Y2;

    int m0 = blockIdx.x * 128, n0 = blockIdx.y * 128;
    int tid = threadIdx.x;
    int lane = tid & 31, warp = tid >> 5;
    int wm = warp & 3, wn = warp >> 2;
    int g = lane >> 2, t = lane & 3;

    float acc[2][8][4];
#pragma unroll
    for (int mt = 0; mt < 2; mt++)
#pragma unroll
        for (int j = 0; j < 8; j++)
#pragma unroll
            for (int c = 0; c < 4; c++) acc[mt][j][c] = 0.f;

    // A loader: row = tid>>1 (2 threads/row), cols (tid&1)*8 + {0,4}
    int arow = tid >> 1;
    int acol = (tid & 1) * 8;
    const float* Aptr = X + (size_t)(m0 + arow) * K + acol;
    int asz = (m0 + arow < M) ? 16 : 0;
    // B loader: k-row = tid>>4, cols (tid&15)*8 + {0,4}
    int brow = tid >> 4;
    int bcol = (tid & 15) * 8;
    const float* Bptr = W + (size_t)brow * HID + n0 + bcol;

    // prologue: stage 0
    {
        uint32_t ad = smaddr(&As[0][arow][acol]);
        CPA16(ad, Aptr, asz);
        CPA16(ad + 16, Aptr + 4, asz);
        uint32_t bd = smaddr(&Bs[0][brow][bcol]);
        CPA16(bd, Bptr, 16);
        CPA16(bd + 16, Bptr + 4, 16);
        CPA_COMMIT();
    }

    const int NT = K / 16;   // 64
    for (int kt = 0; kt < NT; kt++) {
        CPA_WAIT0();
        __syncthreads();
        if (kt + 1 < NT) {
            int st = (kt + 1) & 1;
            int k0 = (kt + 1) * 16;
            uint32_t ad = smaddr(&As[st][arow][acol]);
            CPA16(ad, Aptr + k0, asz);
            CPA16(ad + 16, Aptr + k0 + 4, asz);
            uint32_t bd = smaddr(&Bs[st][brow][bcol]);
            CPA16(bd, Bptr + (size_t)k0 * HID, 16);
            CPA16(bd + 16, Bptr + (size_t)k0 * HID + 4, 16);
            CPA_COMMIT();
        }
        int cur = kt & 1;
#pragma unroll
        for (int ks = 0; ks < 2; ks++) {
            int kb = ks * 8;
            uint32_t af[2][4], bf[8][2];
#pragma unroll
            for (int mt = 0; mt < 2; mt++) {
                int m = wm * 32 + mt * 16 + g;
                af[mt][0] = fu(As[cur][m][kb + t]);
                af[mt][1] = fu(As[cur][m + 8][kb + t]);
                af[mt][2] = fu(As[cur][m][kb + t + 4]);
                af[mt][3] = fu(As[cur][m + 8][kb + t + 4]);
            }
#pragma unroll
            for (int j = 0; j < 8; j++) {
                int n = wn * 64 + j * 8 + g;
                bf[j][0] = fu(Bs[cur][kb + t][n]);
                bf[j][1] = fu(Bs[cur][kb + t + 4][n]);
            }
#pragma unroll
            for (int mt = 0; mt < 2; mt++)
#pragma unroll
                for (int j = 0; j < 8; j++)
                    mma_tf32(acc[mt][j], af[mt], bf[j]);
        }
    }

    // epilogue
#pragma unroll
    for (int mt = 0; mt < 2; mt++) {
#pragma unroll
        for (int rr = 0; rr < 2; rr++) {
            int gm = m0 + wm * 32 + mt * 16 + g + rr * 8;
            if (gm >= M) continue;
            int seq = 0, b = 0, s = 0;
            if (OUT_HEADMAJOR) {
                seq = gm / (BATCH * SA);
                int r = gm - seq * (BATCH * SA);
                b = r / SA;
                s = r - b * SA;
            }
#pragma unroll
            for (int j = 0; j < 8; j++) {
                int n = n0 + wn * 64 + j * 8 + t * 2;
                float2 o = make_float2(acc[mt][j][rr * 2] + bias[n],
                                       acc[mt][j][rr * 2 + 1] + bias[n + 1]);
                if (OUT_HEADMAJOR) {
                    int h = n >> 6, d = n & 63;
                    *(float2*)(Y + (size_t)seq * SEQSTR +
                               (((size_t)b * NH + h) * SA + s) * HD + d) = o;
                } else {
                    *(float2*)(Y + (size_t)gm * HID + n) = o;
                }
            }
        }
    }
}

// ---------------- TF32 flash attention, BQ=128, both dirs fused --------------
// q/k/v: [dir][B, NH, SA, HD]; out: [dir][B, SA, HID]
// Physics biases are per-row softmax-invariant constants -> dropped.
// blockIdx.z: bit0 = b, bit1 = dir. 256 threads = 8 warps, 16 q-rows/warp.
__global__ __launch_bounds__(256) void attn_tf32(
    const float* __restrict__ qall, const float* __restrict__ kall,
    const float* __restrict__ vall, float* __restrict__ attall)
{
    __shared__ __align__(16) float Ks[64][68];   // pad 68
    __shared__ __align__(16) float Vs[64][72];   // pad 72

    int qt = blockIdx.x, h = blockIdx.y;
    int b = blockIdx.z & 1, dir = blockIdx.z >> 1;
    const float* Q  = qall + (size_t)dir * SEQSTR;
    const float* Kx = kall + (size_t)(dir ^ 1) * SEQSTR;
    const float* V  = vall + (size_t)(dir ^ 1) * SEQSTR;
    float* attout   = attall + (size_t)dir * SEQSTR;

    int tid = threadIdx.x;
    int lane = tid & 31, warp = tid >> 5;
    int g = lane >> 2, t = lane & 3;
    const size_t hoff = ((size_t)b * NH + h) * (size_t)SA * HD;
    int q0 = qt * 128;

    // ---- stage Q (raw fp32 bits) in two 64-row passes through Ks ----
    uint32_t qf[8][4];
#pragma unroll
    for (int half = 0; half < 2; half++) {
        for (int i = tid; i < 64 * 16; i += 256) {
            int r = i >> 4, c = (i & 15) * 4;
            int gq = q0 + half * 64 + r;
            int sz = (gq < SA) ? 16 : 0;
            int gqc = (gq < SA) ? gq : (SA - 1);
            CPA16(smaddr(&Ks[r][c]), Q + hoff + (size_t)gqc * HD + c, sz);
        }
        CPA_COMMIT(); CPA_WAIT0();
        __syncthreads();
        if ((warp >> 2) == half) {
            int m = (warp & 3) * 16;
#pragma unroll
            for (int kc = 0; kc < 8; kc++) {
                qf[kc][0] = fu(Ks[m + g][kc * 8 + t]);
                qf[kc][1] = fu(Ks[m + 8 + g][kc * 8 + t]);
                qf[kc][2] = fu(Ks[m + g][kc * 8 + t + 4]);
                qf[kc][3] = fu(Ks[m + 8 + g][kc * 8 + t + 4]);
            }
        }
        __syncthreads();
    }

    float o[8][4];
#pragma unroll
    for (int nd = 0; nd < 8; nd++)
#pragma unroll
        for (int c = 0; c < 4; c++) o[nd][c] = 0.f;
    float mrow0 = -1e30f, mrow1 = -1e30f, lrow0 = 0.f, lrow1 = 0.f;

    for (int k0 = 0; k0 < SA; k0 += 64) {
        __syncthreads();
        for (int i = tid; i < 64 * 16; i += 256) {
            int r = i >> 4, c = (i & 15) * 4;
            int gk = k0 + r;
            int sz = (gk < SA) ? 16 : 0;
            int gkc = (gk < SA) ? gk : (SA - 1);
            CPA16(smaddr(&Ks[r][c]), Kx + hoff + (size_t)gkc * HD + c, sz);
            CPA16(smaddr(&Vs[r][c]), V  + hoff + (size_t)gkc * HD + c, sz);
        }
        CPA_COMMIT(); CPA_WAIT0();
        __syncthreads();

        // ---- S = Q @ K^T (scale applied after) ----
        float s[8][4];
#pragma unroll
        for (int j = 0; j < 8; j++)
#pragma unroll
            for (int c = 0; c < 4; c++) s[j][c] = 0.f;
#pragma unroll
        for (int j = 0; j < 8; j++) {
#pragma unroll
            for (int kc = 0; kc < 8; kc++) {
                uint32_t bf[2];
                bf[0] = fu(Ks[j * 8 + g][kc * 8 + t]);
                bf[1] = fu(Ks[j * 8 + g][kc * 8 + t + 4]);
                mma_tf32(s[j], qf[kc], bf);
            }
        }
#pragma unroll
        for (int j = 0; j < 8; j++) {
            s[j][0] *= 0.125f; s[j][1] *= 0.125f;
            s[j][2] *= 0.125f; s[j][3] *= 0.125f;
        }

        // ---- mask invalid keys ----
        int kvalid = SA - k0;
        if (kvalid < 64) {
#pragma unroll
            for (int j = 0; j < 8; j++) {
                int c0 = j * 8 + t * 2, c1 = c0 + 1;
                if (c0 >= kvalid) { s[j][0] = -1e30f; s[j][2] = -1e30f; }
                if (c1 >= kvalid) { s[j][1] = -1e30f; s[j][3] = -1e30f; }
            }
        }

        // ---- online softmax (rows g, g+8 spread over 4 lanes) ----
        float tm0 = -1e30f, tm1 = -1e30f;
#pragma unroll
        for (int j = 0; j < 8; j++) {
            tm0 = fmaxf(tm0, fmaxf(s[j][0], s[j][1]));
            tm1 = fmaxf(tm1, fmaxf(s[j][2], s[j][3]));
        }
        tm0 = fmaxf(tm0, __shfl_xor_sync(0xffffffffu, tm0, 1));
        tm0 = fmaxf(tm0, __shfl_xor_sync(0xffffffffu, tm0, 2));
        tm1 = fmaxf(tm1, __shfl_xor_sync(0xffffffffu, tm1, 1));
        tm1 = fmaxf(tm1, __shfl_xor_sync(0xffffffffu, tm1, 2));
        float nm0 = fmaxf(mrow0, tm0), nm1 = fmaxf(mrow1, tm1);
        float corr0 = __expf(mrow0 - nm0), corr1 = __expf(mrow1 - nm1);
        float sum0 = 0.f, sum1 = 0.f;
#pragma unroll
        for (int j = 0; j < 8; j++) {
            s[j][0] = __expf(s[j][0] - nm0);
            s[j][1] = __expf(s[j][1] - nm0);
            s[j][2] = __expf(s[j][2] - nm1);
            s[j][3] = __expf(s[j][3] - nm1);
            sum0 += s[j][0] + s[j][1];
            sum1 += s[j][2] + s[j][3];
        }
        sum0 += __shfl_xor_sync(0xffffffffu, sum0, 1);
        sum0 += __shfl_xor_sync(0xffffffffu, sum0, 2);
        sum1 += __shfl_xor_sync(0xffffffffu, sum1, 1);
        sum1 += __shfl_xor_sync(0xffffffffu, sum1, 2);
        lrow0 = lrow0 * corr0 + sum0;  mrow0 = nm0;
        lrow1 = lrow1 * corr1 + sum1;  mrow1 = nm1;
#pragma unroll
        for (int nd = 0; nd < 8; nd++) {
            o[nd][0] *= corr0; o[nd][1] *= corr0;
            o[nd][2] *= corr1; o[nd][3] *= corr1;
        }

        // ---- O += P @ V (P -> A-fragments via shuffles) ----
        int s0l = (lane & 28) + (t >> 1);
#pragma unroll
        for (int j = 0; j < 8; j++) {
            float e0 = __shfl_sync(0xffffffffu, s[j][0], s0l);
            float e1 = __shfl_sync(0xffffffffu, s[j][1], s0l);
            float f0 = __shfl_sync(0xffffffffu, s[j][2], s0l);
            float f1 = __shfl_sync(0xffffffffu, s[j][3], s0l);
            float e2 = __shfl_sync(0xffffffffu, s[j][0], s0l + 2);
            float e3 = __shfl_sync(0xffffffffu, s[j][1], s0l + 2);
            float f2 = __shfl_sync(0xffffffffu, s[j][2], s0l + 2);
            float f3 = __shfl_sync(0xffffffffu, s[j][3], s0l + 2);
            uint32_t af[4];
            af[0] = fu((t & 1) ? e1 : e0);
            af[1] = fu((t & 1) ? f1 : f0);
            af[2] = fu((t & 1) ? e3 : e2);
            af[3] = fu((t & 1) ? f3 : f2);
#pragma unroll
            for (int nd = 0; nd < 8; nd++) {
                uint32_t bf[2];
                bf[0] = fu(Vs[j * 8 + t][nd * 8 + g]);
                bf[1] = fu(Vs[j * 8 + t + 4][nd * 8 + g]);
                mma_tf32(o[nd], af, bf);
            }
        }
    }

    // ---- write attended rows ----
    float inv0 = 1.0f / lrow0, inv1 = 1.0f / lrow1;
    int row0 = q0 + warp * 16 + g, row1 = row0 + 8;
    int cb = h * HD;
#pragma unroll
    for (int nd = 0; nd < 8; nd++) {
        int col = cb + nd * 8 + t * 2;
        if (row0 < SA) {
            float2 v = make_float2(o[nd][0] * inv0, o[nd][1] * inv0);
            *(float2*)(attout + ((size_t)b * SA + row0) * HID + col) = v;
        }
        if (row1 < SA) {
            float2 v = make_float2(o[nd][2] * inv1, o[nd][3] * inv1);
            *(float2*)(attout + ((size_t)b * SA + row1) * HID + col) = v;
        }
    }
}

// ---------------- residual + LayerNorm epilogue ------------------------------
__global__ __launch_bounds__(256) void ln_kernel(
    const float* __restrict__ aug, const float* __restrict__ proj,
    const float* __restrict__ gamma, const float* __restrict__ beta,
    float* __restrict__ out)
{
    int s = blockIdx.x, b = blockIdx.y, seq = blockIdx.z;
    int tid = threadIdx.x;
    size_t roff = (((size_t)seq * BATCH + b) * SA + s) * HID;
    int j = tid * 4;

    float4 a = *(const float4*)(aug + roff + j);
    float4 p = *(const float4*)(proj + roff + j);
    float4 x = make_float4(a.x + p.x, a.y + p.y, a.z + p.z, a.w + p.w);

    __shared__ float wsum[8];
    float lsum = x.x + x.y + x.z + x.w;
#pragma unroll
    for (int m = 16; m >= 1; m >>= 1) lsum += __shfl_xor_sync(0xffffffffu, lsum, m);
    if ((tid & 31) == 0) wsum[tid >> 5] = lsum;
    __syncthreads();
    float tot = 0.f;
#pragma unroll
    for (int w = 0; w < 8; w++) tot += wsum[w];
    float mean = tot * (1.0f / HID);

    float dx = x.x - mean, dy = x.y - mean, dz = x.z - mean, dw = x.w - mean;
    float lvar = dx * dx + dy * dy + dz * dz + dw * dw;
#pragma unroll
    for (int m = 16; m >= 1; m >>= 1) lvar += __shfl_xor_sync(0xffffffffu, lvar, m);
    __syncthreads();
    if ((tid & 31) == 0) wsum[tid >> 5] = lvar;
    __syncthreads();
    float tot2 = 0.f;
#pragma unroll
    for (int w = 0; w < 8; w++) tot2 += wsum[w];
    float rstd = rsqrtf(tot2 * (1.0f / HID) + 1e-5f);

    float4 g = *(const float4*)(gamma + j);
    float4 be = *(const float4*)(beta + j);
    float4 oo = make_float4(dx * rstd * g.x + be.x, dy * rstd * g.y + be.y,
                            dz * rstd * g.z + be.z, dw * rstd * g.w + be.w);
    size_t oidx = (size_t)seq * (2ull * SEQ * HID) + ((size_t)b * SEQ + s) * HID + j;
    *(float4*)(out + oidx) = oo;
}

// ---------------- launch ------------------------------------------------------
extern "C" void kernel_launch(void* const* d_in, const int* in_sizes, int n_in,
                              void* d_out, int out_size)
{
    const float* cnn = (const float*)d_in[0];
    const float* llm = (const float*)d_in[1];
    const float* Wq  = (const float*)d_in[2];  const float* bq = (const float*)d_in[3];
    const float* Wk  = (const float*)d_in[4];  const float* bk = (const float*)d_in[5];
    const float* Wv  = (const float*)d_in[6];  const float* bv = (const float*)d_in[7];
    const float* Wo  = (const float*)d_in[8];  const float* bo = (const float*)d_in[9];
    const float* ee  = (const float*)d_in[10];
    const float* me  = (const float*)d_in[11];
    const float* pe  = (const float*)d_in[12];
    const float* gamma = (const float*)d_in[13];
    const float* beta  = (const float*)d_in[14];

    float *aug, *q, *k, *v, *att, *proj;
    cudaGetSymbolAddress((void**)&aug,  g_aug);
    cudaGetSymbolAddress((void**)&q,    g_q);
    cudaGetSymbolAddress((void**)&k,    g_k);
    cudaGetSymbolAddress((void**)&v,    g_v);
    cudaGetSymbolAddress((void**)&att,  g_att);
    cudaGetSymbolAddress((void**)&proj, g_proj);

    build_aug_kernel<<<dim3(SA, BATCH, 2), 256>>>(cnn, llm, ee, me, pe, aug);

    const int M = MROWS;                              // 8204
    dim3 gqkv((M + 127) / 128, HID / 128, 3);         // (65, 8, 3)
    sgemm_tf32<1><<<gqkv, 256>>>(aug, Wq, Wk, Wv, bq, bk, bv, q, k, v, M);

    dim3 ga((SA + 127) / 128, NH, 4);                 // (17, 16, 4)
    attn_tf32<<<ga, 256>>>(q, k, v, att);

    dim3 go((M + 127) / 128, HID / 128, 1);           // (65, 8)
    sgemm_tf32<0><<<go, 256>>>(att, Wo, Wo, Wo, bo, bo, bo, proj, proj, proj, M);

    ln_kernel<<<dim3(SEQ, BATCH, 2), 256>>>(aug, proj, gamma, beta, (float*)d_out);
}

// round 15
// speedup vs baseline: 1.1738x; 1.1738x over previous
#include <cuda_runtime.h>
#include <cuda_bf16.h>
#include <cstdint>

#define BATCH 2
#define SEQ   2048
#define SA    2051
#define HID   1024
#define NH    16
#define HD    64
#define SEQSTR ((size_t)BATCH * SA * HID)
#define MROWS  (2 * BATCH * SA)          // 8204 rows (both seqs)

// ---------------- scratch ----------------------------------------------------
__device__ float g_aug [2 * BATCH * SA * HID];
__device__ float g_q   [2 * BATCH * NH * SA * HD];
__device__ float g_k   [2 * BATCH * NH * SA * HD];
__device__ float g_v   [2 * BATCH * NH * SA * HD];
__device__ float g_att [2 * BATCH * SA * HID];
__device__ float g_proj[2 * BATCH * SA * HID];

// ---------------- helpers ----------------------------------------------------
__device__ __forceinline__ void mma_tf32(float* c, const uint32_t* a, const uint32_t* b) {
    asm volatile(
        "mma.sync.aligned.m16n8k8.row.col.f32.tf32.tf32.f32 "
        "{%0,%1,%2,%3}, {%4,%5,%6,%7}, {%8,%9}, {%0,%1,%2,%3};"
        : "+f"(c[0]), "+f"(c[1]), "+f"(c[2]), "+f"(c[3])
        : "r"(a[0]), "r"(a[1]), "r"(a[2]), "r"(a[3]), "r"(b[0]), "r"(b[1]));
}

__device__ __forceinline__ uint32_t smaddr(const void* p) {
    return (uint32_t)__cvta_generic_to_shared(p);
}
#define CPA16(dst, src, sz) \
    asm volatile("cp.async.cg.shared.global [%0], [%1], 16, %2;" :: "r"(dst), "l"(src), "r"(sz))
#define CPA_COMMIT() asm volatile("cp.async.commit_group;")
#define CPA_WAIT0()  asm volatile("cp.async.wait_group 0;" ::: "memory")
#define CPA_WAIT1()  asm volatile("cp.async.wait_group 1;" ::: "memory")

__device__ __forceinline__ uint32_t fu(float x) { return __float_as_uint(x); }

// ---------------- build augmented sequences ----------------------------------
__global__ void build_aug_kernel(const float* __restrict__ cnn,
                                 const float* __restrict__ llm,
                                 const float* __restrict__ ee,
                                 const float* __restrict__ me,
                                 const float* __restrict__ pe,
                                 float* __restrict__ aug)
{
    int s = blockIdx.x, b = blockIdx.y, seq = blockIdx.z;
    const float* src;
    if (s < SEQ) src = (seq == 0 ? cnn : llm) + ((size_t)b * SEQ + s) * HID;
    else         src = (s == SEQ ? ee : (s == SEQ + 1 ? me : pe));
    float* dst = aug + (((size_t)seq * BATCH + b) * SA + s) * HID;
    int j = threadIdx.x * 4;
    float4 v = *(const float4*)(src + j);
    *(float4*)(dst + j) = v;
}

// ---------------- TF32 GEMM, 3-stage cp.async pipeline -----------------------
// X [M,1024] row-major, W [1024,1024] row-major. BM=BN=128, BK=16, 256 thr.
// 8 warps: 4(m) x 2(n), warp tile 32x64. blockIdx.z selects (W,bias,Y).
// Raw fp32 bits fed to tf32 mma (hardware truncates low mantissa bits).
template<int OUT_HEADMAJOR>
__global__ __launch_bounds__(256) void sgemm_tf32(
    const float* __restrict__ X,
    const float* __restrict__ W0, const float* __restrict__ W1, const float* __restrict__ W2,
    const float* __restrict__ bias0, const float* __restrict__ bias1, const float* __restrict__ bias2,
    float* __restrict__ Y0, float* __restrict__ Y1, float* __restrict__ Y2,
    int M)
{
    __shared__ __align__(16) float As[3][128][20];   // [m][k]: banks 20g+t all distinct
    __shared__ __align__(16) float Bs[3][16][136];   // [k][n]: banks 8t+g all distinct

    const int K = 1024;
    int z = blockIdx.z;
    const float* W    = (z == 0) ? W0 : (z == 1) ? W1 : W2;
    const float* bias = (z == 0) ? bias0 : (z == 1) ? bias1 : bias2;
    float*       Y    = (z == 0) ? Y0 : (z == 1) ? Y1 : Y2;

    int m0 = blockIdx.x * 128, n0 = blockIdx.y * 128;
    int tid = threadIdx.x;
    int lane = tid & 31, warp = tid >> 5;
    int wm = warp & 3, wn = warp >> 2;
    int g = lane >> 2, t = lane & 3;

    float acc[2][8][4];
#pragma unroll
    for (int mt = 0; mt < 2; mt++)
#pragma unroll
        for (int j = 0; j < 8; j++)
#pragma unroll
            for (int c = 0; c < 4; c++) acc[mt][j][c] = 0.f;

    // A loader: row = tid>>1, cols (tid&1)*8 + {0,4}
    int arow = tid >> 1;
    int acol = (tid & 1) * 8;
    const float* Aptr = X + (size_t)(m0 + arow) * K + acol;
    int asz = (m0 + arow < M) ? 16 : 0;
    // B loader: k-row = tid>>4, cols (tid&15)*8 + {0,4}
    int brow = tid >> 4;
    int bcol = (tid & 15) * 8;
    const float* Bptr = W + (size_t)brow * HID + n0 + bcol;

    const int NT = K / 16;   // 64

    // prologue: stages 0, 1
#pragma unroll
    for (int st = 0; st < 2; st++) {
        int k0 = st * 16;
        uint32_t ad = smaddr(&As[st][arow][acol]);
        CPA16(ad, Aptr + k0, asz);
        CPA16(ad + 16, Aptr + k0 + 4, asz);
        uint32_t bd = smaddr(&Bs[st][brow][bcol]);
        CPA16(bd, Bptr + (size_t)k0 * HID, 16);
        CPA16(bd + 16, Bptr + (size_t)k0 * HID + 4, 16);
        CPA_COMMIT();
    }

    int cur = 0;
    for (int kt = 0; kt < NT; kt++) {
        if (kt == NT - 1) { CPA_WAIT0(); } else { CPA_WAIT1(); }
        __syncthreads();
        if (kt + 2 < NT) {
            int st = cur == 0 ? 2 : cur - 1;   // (kt+2) % 3
            int k0 = (kt + 2) * 16;
            uint32_t ad = smaddr(&As[st][arow][acol]);
            CPA16(ad, Aptr + k0, asz);
            CPA16(ad + 16, Aptr + k0 + 4, asz);
            uint32_t bd = smaddr(&Bs[st][brow][bcol]);
            CPA16(bd, Bptr + (size_t)k0 * HID, 16);
            CPA16(bd + 16, Bptr + (size_t)k0 * HID + 4, 16);
            CPA_COMMIT();
        }
#pragma unroll
        for (int ks = 0; ks < 2; ks++) {
            int kb = ks * 8;
            uint32_t af[2][4], bf[8][2];
#pragma unroll
            for (int mt = 0; mt < 2; mt++) {
                int m = wm * 32 + mt * 16 + g;
                af[mt][0] = fu(As[cur][m][kb + t]);
                af[mt][1] = fu(As[cur][m + 8][kb + t]);
                af[mt][2] = fu(As[cur][m][kb + t + 4]);
                af[mt][3] = fu(As[cur][m + 8][kb + t + 4]);
            }
#pragma unroll
            for (int j = 0; j < 8; j++) {
                int n = wn * 64 + j * 8 + g;
                bf[j][0] = fu(Bs[cur][kb + t][n]);
                bf[j][1] = fu(Bs[cur][kb + t + 4][n]);
            }
#pragma unroll
            for (int mt = 0; mt < 2; mt++)
#pragma unroll
                for (int j = 0; j < 8; j++)
                    mma_tf32(acc[mt][j], af[mt], bf[j]);
        }
        cur = (cur == 2) ? 0 : cur + 1;
    }

    // epilogue
#pragma unroll
    for (int mt = 0; mt < 2; mt++) {
#pragma unroll
        for (int rr = 0; rr < 2; rr++) {
            int gm = m0 + wm * 32 + mt * 16 + g + rr * 8;
            if (gm >= M) continue;
            int seq = 0, b = 0, s = 0;
            if (OUT_HEADMAJOR) {
                seq = gm / (BATCH * SA);
                int r = gm - seq * (BATCH * SA);
                b = r / SA;
                s = r - b * SA;
            }
#pragma unroll
            for (int j = 0; j < 8; j++) {
                int n = n0 + wn * 64 + j * 8 + t * 2;
                float2 o = make_float2(acc[mt][j][rr * 2] + bias[n],
                                       acc[mt][j][rr * 2 + 1] + bias[n + 1]);
                if (OUT_HEADMAJOR) {
                    int h = n >> 6, d = n & 63;
                    *(float2*)(Y + (size_t)seq * SEQSTR +
                               (((size_t)b * NH + h) * SA + s) * HD + d) = o;
                } else {
                    *(float2*)(Y + (size_t)gm * HID + n) = o;
                }
            }
        }
    }
}

// ---------------- TF32 flash attention, BQ=128, both dirs fused --------------
// q/k/v: [dir][B, NH, SA, HD]; out: [dir][B, SA, HID]
// Physics biases are per-row softmax-invariant constants -> dropped.
// LDG->STS loader (R13 structure), raw fp32 bits (no cvt).
// blockIdx.z: bit0 = b, bit1 = dir. 256 threads = 8 warps, 16 q-rows/warp.
__global__ __launch_bounds__(256) void attn_tf32(
    const float* __restrict__ qall, const float* __restrict__ kall,
    const float* __restrict__ vall, float* __restrict__ attall)
{
    __shared__ __align__(16) float Ks[64][68];   // pad 68 (== 4 mod 32)
    __shared__ __align__(16) float Vs[64][72];   // pad 72 (== 8 mod 32)

    int qt = blockIdx.x, h = blockIdx.y;
    int b = blockIdx.z & 1, dir = blockIdx.z >> 1;
    const float* Q  = qall + (size_t)dir * SEQSTR;
    const float* Kx = kall + (size_t)(dir ^ 1) * SEQSTR;
    const float* V  = vall + (size_t)(dir ^ 1) * SEQSTR;
    float* attout   = attall + (size_t)dir * SEQSTR;

    int tid = threadIdx.x;
    int lane = tid & 31, warp = tid >> 5;
    int g = lane >> 2, t = lane & 3;
    const size_t hoff = ((size_t)b * NH + h) * (size_t)SA * HD;
    int q0 = qt * 128;

    // ---- stage Q (scaled by 1/8, raw bits) in two 64-row passes ----
    uint32_t qf[8][4];
#pragma unroll
    for (int half = 0; half < 2; half++) {
        for (int i = tid; i < 64 * 16; i += 256) {
            int r = i >> 4, c = (i & 15) * 4;
            int gq = q0 + half * 64 + r;
            float4 v = make_float4(0.f, 0.f, 0.f, 0.f);
            if (gq < SA) v = *(const float4*)(Q + hoff + (size_t)gq * HD + c);
            v.x *= 0.125f; v.y *= 0.125f; v.z *= 0.125f; v.w *= 0.125f;
            *(float4*)(&Ks[r][c]) = v;
        }
        __syncthreads();
        if ((warp >> 2) == half) {
            int m = (warp & 3) * 16;
#pragma unroll
            for (int kc = 0; kc < 8; kc++) {
                qf[kc][0] = fu(Ks[m + g][kc * 8 + t]);
                qf[kc][1] = fu(Ks[m + 8 + g][kc * 8 + t]);
                qf[kc][2] = fu(Ks[m + g][kc * 8 + t + 4]);
                qf[kc][3] = fu(Ks[m + 8 + g][kc * 8 + t + 4]);
            }
        }
        __syncthreads();
    }

    float o[8][4];
#pragma unroll
    for (int nd = 0; nd < 8; nd++)
#pragma unroll
        for (int c = 0; c < 4; c++) o[nd][c] = 0.f;
    float mrow0 = -1e30f, mrow1 = -1e30f, lrow0 = 0.f, lrow1 = 0.f;

    for (int k0 = 0; k0 < SA; k0 += 64) {
        __syncthreads();
        for (int i = tid; i < 64 * 16; i += 256) {
            int r = i >> 4, c = (i & 15) * 4;
            int gk = k0 + r;
            float4 kv = make_float4(0.f, 0.f, 0.f, 0.f), vv = kv;
            if (gk < SA) {
                kv = *(const float4*)(Kx + hoff + (size_t)gk * HD + c);
                vv = *(const float4*)(V  + hoff + (size_t)gk * HD + c);
            }
            *(float4*)(&Ks[r][c]) = kv;
            *(float4*)(&Vs[r][c]) = vv;
        }
        __syncthreads();

        // ---- S = (Q/8) @ K^T ----
        float s[8][4];
#pragma unroll
        for (int j = 0; j < 8; j++)
#pragma unroll
            for (int c = 0; c < 4; c++) s[j][c] = 0.f;
#pragma unroll
        for (int j = 0; j < 8; j++) {
#pragma unroll
            for (int kc = 0; kc < 8; kc++) {
                uint32_t bf[2];
                bf[0] = fu(Ks[j * 8 + g][kc * 8 + t]);
                bf[1] = fu(Ks[j * 8 + g][kc * 8 + t + 4]);
                mma_tf32(s[j], qf[kc], bf);
            }
        }

        // ---- mask invalid keys ----
        int kvalid = SA - k0;
        if (kvalid < 64) {
#pragma unroll
            for (int j = 0; j < 8; j++) {
                int c0 = j * 8 + t * 2, c1 = c0 + 1;
                if (c0 >= kvalid) { s[j][0] = -1e30f; s[j][2] = -1e30f; }
                if (c1 >= kvalid) { s[j][1] = -1e30f; s[j][3] = -1e30f; }
            }
        }

        // ---- online softmax (rows g, g+8 spread over 4 lanes) ----
        float tm0 = -1e30f, tm1 = -1e30f;
#pragma unroll
        for (int j = 0; j < 8; j++) {
            tm0 = fmaxf(tm0, fmaxf(s[j][0], s[j][1]));
            tm1 = fmaxf(tm1, fmaxf(s[j][2], s[j][3]));
        }
        tm0 = fmaxf(tm0, __shfl_xor_sync(0xffffffffu, tm0, 1));
        tm0 = fmaxf(tm0, __shfl_xor_sync(0xffffffffu, tm0, 2));
        tm1 = fmaxf(tm1, __shfl_xor_sync(0xffffffffu, tm1, 1));
        tm1 = fmaxf(tm1, __shfl_xor_sync(0xffffffffu, tm1, 2));
        float nm0 = fmaxf(mrow0, tm0), nm1 = fmaxf(mrow1, tm1);
        float corr0 = __expf(mrow0 - nm0), corr1 = __expf(mrow1 - nm1);
        float sum0 = 0.f, sum1 = 0.f;
#pragma unroll
        for (int j = 0; j < 8; j++) {
            s[j][0] = __expf(s[j][0] - nm0);
            s[j][1] = __expf(s[j][1] - nm0);
            s[j][2] = __expf(s[j][2] - nm1);
            s[j][3] = __expf(s[j][3] - nm1);
            sum0 += s[j][0] + s[j][1];
            sum1 += s[j][2] + s[j][3];
        }
        sum0 += __shfl_xor_sync(0xffffffffu, sum0, 1);
        sum0 += __shfl_xor_sync(0xffffffffu, sum0, 2);
        sum1 += __shfl_xor_sync(0xffffffffu, sum1, 1);
        sum1 += __shfl_xor_sync(0xffffffffu, sum1, 2);
        lrow0 = lrow0 * corr0 + sum0;  mrow0 = nm0;
        lrow1 = lrow1 * corr1 + sum1;  mrow1 = nm1;
#pragma unroll
        for (int nd = 0; nd < 8; nd++) {
            o[nd][0] *= corr0; o[nd][1] *= corr0;
            o[nd][2] *= corr1; o[nd][3] *= corr1;
        }

        // ---- O += P @ V (P -> A-fragments via shuffles) ----
        int s0l = (lane & 28) + (t >> 1);
#pragma unroll
        for (int j = 0; j < 8; j++) {
            float e0 = __shfl_sync(0xffffffffu, s[j][0], s0l);
            float e1 = __shfl_sync(0xffffffffu, s[j][1], s0l);
            float f0 = __shfl_sync(0xffffffffu, s[j][2], s0l);
            float f1 = __shfl_sync(0xffffffffu, s[j][3], s0l);
            float e2 = __shfl_sync(0xffffffffu, s[j][0], s0l + 2);
            float e3 = __shfl_sync(0xffffffffu, s[j][1], s0l + 2);
            float f2 = __shfl_sync(0xffffffffu, s[j][2], s0l + 2);
            float f3 = __shfl_sync(0xffffffffu, s[j][3], s0l + 2);
            uint32_t af[4];
            af[0] = fu((t & 1) ? e1 : e0);
            af[1] = fu((t & 1) ? f1 : f0);
            af[2] = fu((t & 1) ? e3 : e2);
            af[3] = fu((t & 1) ? f3 : f2);
#pragma unroll
            for (int nd = 0; nd < 8; nd++) {
                uint32_t bf[2];
                bf[0] = fu(Vs[j * 8 + t][nd * 8 + g]);
                bf[1] = fu(Vs[j * 8 + t + 4][nd * 8 + g]);
                mma_tf32(o[nd], af, bf);
            }
        }
    }

    // ---- write attended rows ----
    float inv0 = 1.0f / lrow0, inv1 = 1.0f / lrow1;
    int row0 = q0 + warp * 16 + g, row1 = row0 + 8;
    int cb = h * HD;
#pragma unroll
    for (int nd = 0; nd < 8; nd++) {
        int col = cb + nd * 8 + t * 2;
        if (row0 < SA) {
            float2 v = make_float2(o[nd][0] * inv0, o[nd][1] * inv0);
            *(float2*)(attout + ((size_t)b * SA + row0) * HID + col) = v;
        }
        if (row1 < SA) {
            float2 v = make_float2(o[nd][2] * inv1, o[nd][3] * inv1);
            *(float2*)(attout + ((size_t)b * SA + row1) * HID + col) = v;
        }
    }
}

// ---------------- residual + LayerNorm epilogue ------------------------------
__global__ __launch_bounds__(256) void ln_kernel(
    const float* __restrict__ aug, const float* __restrict__ proj,
    const float* __restrict__ gamma, const float* __restrict__ beta,
    float* __restrict__ out)
{
    int s = blockIdx.x, b = blockIdx.y, seq = blockIdx.z;
    int tid = threadIdx.x;
    size_t roff = (((size_t)seq * BATCH + b) * SA + s) * HID;
    int j = tid * 4;

    float4 a = *(const float4*)(aug + roff + j);
    float4 p = *(const float4*)(proj + roff + j);
    float4 x = make_float4(a.x + p.x, a.y + p.y, a.z + p.z, a.w + p.w);

    __shared__ float wsum[8];
    float lsum = x.x + x.y + x.z + x.w;
#pragma unroll
    for (int m = 16; m >= 1; m >>= 1) lsum += __shfl_xor_sync(0xffffffffu, lsum, m);
    if ((tid & 31) == 0) wsum[tid >> 5] = lsum;
    __syncthreads();
    float tot = 0.f;
#pragma unroll
    for (int w = 0; w < 8; w++) tot += wsum[w];
    float mean = tot * (1.0f / HID);

    float dx = x.x - mean, dy = x.y - mean, dz = x.z - mean, dw = x.w - mean;
    float lvar = dx * dx + dy * dy + dz * dz + dw * dw;
#pragma unroll
    for (int m = 16; m >= 1; m >>= 1) lvar += __shfl_xor_sync(0xffffffffu, lvar, m);
    __syncthreads();
    if ((tid & 31) == 0) wsum[tid >> 5] = lvar;
    __syncthreads();
    float tot2 = 0.f;
#pragma unroll
    for (int w = 0; w < 8; w++) tot2 += wsum[w];
    float rstd = rsqrtf(tot2 * (1.0f / HID) + 1e-5f);

    float4 g = *(const float4*)(gamma + j);
    float4 be = *(const float4*)(beta + j);
    float4 oo = make_float4(dx * rstd * g.x + be.x, dy * rstd * g.y + be.y,
                            dz * rstd * g.z + be.z, dw * rstd * g.w + be.w);
    size_t oidx = (size_t)seq * (2ull * SEQ * HID) + ((size_t)b * SEQ + s) * HID + j;
    *(float4*)(out + oidx) = oo;
}

// ---------------- launch ------------------------------------------------------
extern "C" void kernel_launch(void* const* d_in, const int* in_sizes, int n_in,
                              void* d_out, int out_size)
{
    const float* cnn = (const float*)d_in[0];
    const float* llm = (const float*)d_in[1];
    const float* Wq  = (const float*)d_in[2];  const float* bq = (const float*)d_in[3];
    const float* Wk  = (const float*)d_in[4];  const float* bk = (const float*)d_in[5];
    const float* Wv  = (const float*)d_in[6];  const float* bv = (const float*)d_in[7];
    const float* Wo  = (const float*)d_in[8];  const float* bo = (const float*)d_in[9];
    const float* ee  = (const float*)d_in[10];
    const float* me  = (const float*)d_in[11];
    const float* pe  = (const float*)d_in[12];
    const float* gamma = (const float*)d_in[13];
    const float* beta  = (const float*)d_in[14];

    float *aug, *q, *k, *v, *att, *proj;
    cudaGetSymbolAddress((void**)&aug,  g_aug);
    cudaGetSymbolAddress((void**)&q,    g_q);
    cudaGetSymbolAddress((void**)&k,    g_k);
    cudaGetSymbolAddress((void**)&v,    g_v);
    cudaGetSymbolAddress((void**)&att,  g_att);
    cudaGetSymbolAddress((void**)&proj, g_proj);

    build_aug_kernel<<<dim3(SA, BATCH, 2), 256>>>(cnn, llm, ee, me, pe, aug);

    const int M = MROWS;                              // 8204
    dim3 gqkv((M + 127) / 128, HID / 128, 3);         // (65, 8, 3)
    sgemm_tf32<1><<<gqkv, 256>>>(aug, Wq, Wk, Wv, bq, bk, bv, q, k, v, M);

    dim3 ga((SA + 127) / 128, NH, 4);                 // (17, 16, 4)
    attn_tf32<<<ga, 256>>>(q, k, v, att);

    dim3 go((M + 127) / 128, HID / 128, 1);           // (65, 8)
    sgemm_tf32<0><<<go, 256>>>(att, Wo, Wo, Wo, bo, bo, bo, proj, proj, proj, M);

    ln_kernel<<<dim3(SEQ, BATCH, 2), 256>>>(aug, proj, gamma, beta, (float*)d_out);
}

// round 16
// speedup vs baseline: 2.2889x; 1.9501x over previous
#include <cuda_runtime.h>
#include <cuda_bf16.h>
#include <cstdint>

typedef __nv_bfloat16 bf16;

#define BATCH 2
#define SEQ   2048
#define SA    2051
#define HID   1024
#define NH    16
#define HD    64
#define SEQSTR ((size_t)BATCH * SA * HID)
#define MROWS  (2 * BATCH * SA)          // 8204

// ---------------- scratch ----------------------------------------------------
__device__ float g_aug [2 * BATCH * SA * HID];    // fp32 (residual)
__device__ bf16  g_augh[2 * BATCH * SA * HID];    // bf16 (GEMM input)
__device__ bf16  g_q   [2 * BATCH * NH * SA * HD];
__device__ bf16  g_k   [2 * BATCH * NH * SA * HD];
__device__ bf16  g_v   [2 * BATCH * NH * SA * HD];
__device__ bf16  g_att [2 * BATCH * SA * HID];
__device__ float g_proj[2 * BATCH * SA * HID];
__device__ bf16  g_wh  [4][HID * HID];            // bf16 weights

// ---------------- helpers ----------------------------------------------------
__device__ __forceinline__ void mma_bf16(float* c, const uint32_t* a, const uint32_t* b) {
    asm volatile(
        "mma.sync.aligned.m16n8k16.row.col.f32.bf16.bf16.f32 "
        "{%0,%1,%2,%3}, {%4,%5,%6,%7}, {%8,%9}, {%0,%1,%2,%3};"
        : "+f"(c[0]), "+f"(c[1]), "+f"(c[2]), "+f"(c[3])
        : "r"(a[0]), "r"(a[1]), "r"(a[2]), "r"(a[3]), "r"(b[0]), "r"(b[1]));
}
__device__ __forceinline__ uint32_t smaddr(const void* p) {
    return (uint32_t)__cvta_generic_to_shared(p);
}
#define CPA16(dst, src, sz) \
    asm volatile("cp.async.cg.shared.global [%0], [%1], 16, %2;" :: "r"(dst), "l"(src), "r"(sz))
#define CPA_COMMIT() asm volatile("cp.async.commit_group;")
#define CPA_WAIT0()  asm volatile("cp.async.wait_group 0;" ::: "memory")
#define CPA_WAIT1()  asm volatile("cp.async.wait_group 1;" ::: "memory")
#define LDSM4T(r0, r1, r2, r3, addr) \
    asm volatile("ldmatrix.sync.aligned.m8n8.x4.trans.shared.b16 {%0,%1,%2,%3}, [%4];" \
        : "=r"(r0), "=r"(r1), "=r"(r2), "=r"(r3) : "r"(addr))

__device__ __forceinline__ uint32_t packbf(float lo, float hi) {
    uint32_t r;
    asm("cvt.rn.bf16x2.f32 %0, %1, %2;" : "=r"(r) : "f"(hi), "f"(lo));
    return r;
}
__device__ __forceinline__ uint32_t ldu32(const bf16* p) {
    return *(const uint32_t*)p;
}

// ---------------- build augmented sequences (fp32 + bf16) --------------------
__global__ void build_aug_kernel(const float* __restrict__ cnn,
                                 const float* __restrict__ llm,
                                 const float* __restrict__ ee,
                                 const float* __restrict__ me,
                                 const float* __restrict__ pe,
                                 float* __restrict__ aug,
                                 bf16* __restrict__ augh)
{
    int s = blockIdx.x, b = blockIdx.y, seq = blockIdx.z;
    const float* src;
    if (s < SEQ) src = (seq == 0 ? cnn : llm) + ((size_t)b * SEQ + s) * HID;
    else         src = (s == SEQ ? ee : (s == SEQ + 1 ? me : pe));
    size_t off = (((size_t)seq * BATCH + b) * SA + s) * HID;
    int j = threadIdx.x * 4;
    float4 v = *(const float4*)(src + j);
    *(float4*)(aug + off + j) = v;
    uint32_t p0 = packbf(v.x, v.y), p1 = packbf(v.z, v.w);
    *(uint32_t*)(augh + off + j) = p0;
    *(uint32_t*)(augh + off + j + 2) = p1;
}

// ---------------- weight fp32 -> bf16 ----------------------------------------
__global__ void conv_w_kernel(const float* __restrict__ W0, const float* __restrict__ W1,
                              const float* __restrict__ W2, const float* __restrict__ W3,
                              bf16* __restrict__ Wh)
{
    int z = blockIdx.y;
    const float* W = (z == 0) ? W0 : (z == 1) ? W1 : (z == 2) ? W2 : W3;
    size_t i = ((size_t)blockIdx.x * 256 + threadIdx.x) * 4;
    float4 v = *(const float4*)(W + i);
    bf16* dst = Wh + (size_t)z * HID * HID + i;
    *(uint32_t*)(dst)     = packbf(v.x, v.y);
    *(uint32_t*)(dst + 2) = packbf(v.z, v.w);
}

// ---------------- BF16 GEMM, 3-stage cp.async, BK=32 -------------------------
// X [M,1024] bf16 row-major, W [1024,1024] bf16 row-major.
// BM=BN=128, BK=32, 256 thr, 8 warps (4m x 2n), warp tile 32x64.
// HEADMAJOR=1: Y bf16 [seq][b][h][s][d]; HEADMAJOR=0: Y fp32 row-major.
template<int HEADMAJOR>
__global__ __launch_bounds__(256) void gemm_bf16(
    const bf16* __restrict__ X, const bf16* __restrict__ Wh,
    const float* __restrict__ bias0, const float* __restrict__ bias1, const float* __restrict__ bias2,
    void* __restrict__ Y0, void* __restrict__ Y1, void* __restrict__ Y2,
    int M)
{
    __shared__ __align__(16) bf16 As[3][128][40];   // stride 20 words: banks 20g+t distinct
    __shared__ __align__(16) bf16 Bs[3][32][136];   // stride 68 words: ldmatrix phases clean

    const int K = 1024;
    int z = blockIdx.z;
    const bf16* W     = Wh + (size_t)z * HID * HID;
    const float* bias = (z == 0) ? bias0 : (z == 1) ? bias1 : bias2;
    void*       Y     = (z == 0) ? Y0 : (z == 1) ? Y1 : Y2;

    int m0 = blockIdx.x * 128, n0 = blockIdx.y * 128;
    int tid = threadIdx.x;
    int lane = tid & 31, warp = tid >> 5;
    int wm = warp & 3, wn = warp >> 2;
    int g = lane >> 2, t = lane & 3;

    float acc[2][8][4];
#pragma unroll
    for (int mt = 0; mt < 2; mt++)
#pragma unroll
        for (int j = 0; j < 8; j++)
#pragma unroll
            for (int c = 0; c < 4; c++) acc[mt][j][c] = 0.f;

    // A loader: row tid>>1, 2 chunks of 8 bf16 at (tid&1)*16
    int arow = tid >> 1;
    int aoff = (tid & 1) * 16;
    const bf16* Aptr = X + (size_t)(m0 + arow) * K + aoff;
    int asz = (m0 + arow < M) ? 16 : 0;
    // B loader: k-row tid>>3, 2 chunks at (tid&7)*16
    int brow = tid >> 3;
    int boff = (tid & 7) * 16;
    const bf16* Bptr = W + (size_t)brow * HID + n0 + boff;

    const int NT = K / 32;   // 32

    // prologue: stages 0, 1
#pragma unroll
    for (int st = 0; st < 2; st++) {
        int k0 = st * 32;
        uint32_t ad = smaddr(&As[st][arow][aoff]);
        CPA16(ad, Aptr + k0, asz);
        CPA16(ad + 16, Aptr + k0 + 8, asz);
        uint32_t bd = smaddr(&Bs[st][brow][boff]);
        CPA16(bd, Bptr + (size_t)k0 * HID, 16);
        CPA16(bd + 16, Bptr + (size_t)k0 * HID + 8, 16);
        CPA_COMMIT();
    }

    int cur = 0;
    for (int kt = 0; kt < NT; kt++) {
        if (kt == NT - 1) { CPA_WAIT0(); } else { CPA_WAIT1(); }
        __syncthreads();
        if (kt + 2 < NT) {
            int st = cur == 0 ? 2 : cur - 1;   // (kt+2) % 3
            int k0 = (kt + 2) * 32;
            uint32_t ad = smaddr(&As[st][arow][aoff]);
            CPA16(ad, Aptr + k0, asz);
            CPA16(ad + 16, Aptr + k0 + 8, asz);
            uint32_t bd = smaddr(&Bs[st][brow][boff]);
            CPA16(bd, Bptr + (size_t)k0 * HID, 16);
            CPA16(bd + 16, Bptr + (size_t)k0 * HID + 8, 16);
            CPA_COMMIT();
        }
#pragma unroll
        for (int ks = 0; ks < 2; ks++) {
            int kb = ks * 16;
            uint32_t af[2][4], bf[8][2];
#pragma unroll
            for (int mt = 0; mt < 2; mt++) {
                int m = wm * 32 + mt * 16 + g;
                af[mt][0] = ldu32(&As[cur][m][kb + 2 * t]);
                af[mt][1] = ldu32(&As[cur][m + 8][kb + 2 * t]);
                af[mt][2] = ldu32(&As[cur][m][kb + 2 * t + 8]);
                af[mt][3] = ldu32(&As[cur][m + 8][kb + 2 * t + 8]);
            }
#pragma unroll
            for (int jj = 0; jj < 4; jj++) {
                int row = kb + ((lane >> 3) & 1) * 8 + (lane & 7);
                int col = wn * 64 + jj * 16 + (lane >> 4) * 8;
                uint32_t a = smaddr(&Bs[cur][row][col]);
                LDSM4T(bf[jj * 2][0], bf[jj * 2][1], bf[jj * 2 + 1][0], bf[jj * 2 + 1][1], a);
            }
#pragma unroll
            for (int mt = 0; mt < 2; mt++)
#pragma unroll
                for (int j = 0; j < 8; j++)
                    mma_bf16(acc[mt][j], af[mt], bf[j]);
        }
        cur = (cur == 2) ? 0 : cur + 1;
    }

    // epilogue
#pragma unroll
    for (int mt = 0; mt < 2; mt++) {
#pragma unroll
        for (int rr = 0; rr < 2; rr++) {
            int gm = m0 + wm * 32 + mt * 16 + g + rr * 8;
            if (gm >= M) continue;
            int seq = 0, b = 0, s = 0;
            if (HEADMAJOR) {
                seq = gm / (BATCH * SA);
                int r = gm - seq * (BATCH * SA);
                b = r / SA;
                s = r - b * SA;
            }
#pragma unroll
            for (int j = 0; j < 8; j++) {
                int n = n0 + wn * 64 + j * 8 + t * 2;
                float o0 = acc[mt][j][rr * 2] + bias[n];
                float o1 = acc[mt][j][rr * 2 + 1] + bias[n + 1];
                if (HEADMAJOR) {
                    int h = n >> 6, d = n & 63;
                    bf16* yp = (bf16*)Y + (size_t)seq * SEQSTR +
                               (((size_t)b * NH + h) * SA + s) * HD + d;
                    *(uint32_t*)yp = packbf(o0, o1);
                } else {
                    *(float2*)((float*)Y + (size_t)gm * HID + n) = make_float2(o0, o1);
                }
            }
        }
    }
}

// ---------------- BF16 flash attention, BQ=128, 2-stage KV pipeline ----------
// q/k/v bf16 [dir][B, NH, SA, HD]; att bf16 [dir][B, SA, HID]
// Physics biases are per-row softmax-invariant constants -> dropped.
// blockIdx.z: bit0 = b, bit1 = dir. 256 thr = 8 warps, 16 q-rows/warp.
__global__ __launch_bounds__(256) void attn_bf16(
    const bf16* __restrict__ qall, const bf16* __restrict__ kall,
    const bf16* __restrict__ vall, bf16* __restrict__ attall)
{
    __shared__ __align__(16) bf16 Qs[128][72];      // stride 36 words: banks 4g+t distinct
    __shared__ __align__(16) bf16 Ks[2][64][72];
    __shared__ __align__(16) bf16 Vs[2][64][72];

    int qt = blockIdx.x, h = blockIdx.y;
    int b = blockIdx.z & 1, dir = blockIdx.z >> 1;
    const bf16* Q  = qall + (size_t)dir * SEQSTR;
    const bf16* Kx = kall + (size_t)(dir ^ 1) * SEQSTR;
    const bf16* V  = vall + (size_t)(dir ^ 1) * SEQSTR;
    bf16* attout   = attall + (size_t)dir * SEQSTR;

    int tid = threadIdx.x;
    int lane = tid & 31, warp = tid >> 5;
    int g = lane >> 2, t = lane & 3;
    const size_t hoff = ((size_t)b * NH + h) * (size_t)SA * HD;
    int q0 = qt * 128;

    // ---- prologue: stage Q (128 rows) + KV tile 0, one cp.async group ----
#pragma unroll
    for (int i = tid; i < 128 * 8; i += 256) {       // 4 iters
        int r = i >> 3, c = (i & 7) * 8;
        int gq = q0 + r;
        int sz = (gq < SA) ? 16 : 0;
        int gqc = (gq < SA) ? gq : (SA - 1);
        CPA16(smaddr(&Qs[r][c]), Q + hoff + (size_t)gqc * HD + c, sz);
    }
#pragma unroll
    for (int i = tid; i < 64 * 8; i += 256) {        // 2 iters
        int r = i >> 3, c = (i & 7) * 8;
        int sz = (r < SA) ? 16 : 0;                  // tile 0: rows 0..63 all < SA
        CPA16(smaddr(&Ks[0][r][c]), Kx + hoff + (size_t)r * HD + c, sz);
        CPA16(smaddr(&Vs[0][r][c]), V  + hoff + (size_t)r * HD + c, sz);
    }
    CPA_COMMIT();
    CPA_WAIT0();
    __syncthreads();

    // ---- Q fragments (held in regs for whole kernel) ----
    uint32_t qf[4][4];
    {
        int m = warp * 16;
#pragma unroll
        for (int kc = 0; kc < 4; kc++) {
            qf[kc][0] = ldu32(&Qs[m + g][kc * 16 + 2 * t]);
            qf[kc][1] = ldu32(&Qs[m + 8 + g][kc * 16 + 2 * t]);
            qf[kc][2] = ldu32(&Qs[m + g][kc * 16 + 2 * t + 8]);
            qf[kc][3] = ldu32(&Qs[m + 8 + g][kc * 16 + 2 * t + 8]);
        }
    }

    float o[8][4];
#pragma unroll
    for (int nd = 0; nd < 8; nd++)
#pragma unroll
        for (int c = 0; c < 4; c++) o[nd][c] = 0.f;
    float mrow0 = -1e30f, mrow1 = -1e30f, lrow0 = 0.f, lrow1 = 0.f;

    const int NT = (SA + 63) / 64;   // 33
    for (int kt = 0; kt < NT; kt++) {
        __syncthreads();   // all warps done with buffer (kt+1)&1 from iter kt-1
        if (kt + 1 < NT) {
            int nb = (kt + 1) & 1;
            int kbase = (kt + 1) * 64;
#pragma unroll
            for (int i = tid; i < 64 * 8; i += 256) {
                int r = i >> 3, c = (i & 7) * 8;
                int gk = kbase + r;
                int sz = (gk < SA) ? 16 : 0;
                int gkc = (gk < SA) ? gk : (SA - 1);
                CPA16(smaddr(&Ks[nb][r][c]), Kx + hoff + (size_t)gkc * HD + c, sz);
                CPA16(smaddr(&Vs[nb][r][c]), V  + hoff + (size_t)gkc * HD + c, sz);
            }
            CPA_COMMIT();
            CPA_WAIT1();
        } else {
            CPA_WAIT0();
        }
        __syncthreads();
        int buf = kt & 1;

        // ---- S = Q @ K^T (scale after) ----
        float s[8][4];
#pragma unroll
        for (int j = 0; j < 8; j++)
#pragma unroll
            for (int c = 0; c < 4; c++) s[j][c] = 0.f;
#pragma unroll
        for (int j = 0; j < 8; j++) {
#pragma unroll
            for (int kc = 0; kc < 4; kc++) {
                uint32_t bfr[2];
                bfr[0] = ldu32(&Ks[buf][j * 8 + g][kc * 16 + 2 * t]);
                bfr[1] = ldu32(&Ks[buf][j * 8 + g][kc * 16 + 2 * t + 8]);
                mma_bf16(s[j], qf[kc], bfr);
            }
        }
#pragma unroll
        for (int j = 0; j < 8; j++) {
            s[j][0] *= 0.125f; s[j][1] *= 0.125f;
            s[j][2] *= 0.125f; s[j][3] *= 0.125f;
        }

        // ---- mask invalid keys ----
        int kvalid = SA - kt * 64;
        if (kvalid < 64) {
#pragma unroll
            for (int j = 0; j < 8; j++) {
                int c0 = j * 8 + t * 2, c1 = c0 + 1;
                if (c0 >= kvalid) { s[j][0] = -1e30f; s[j][2] = -1e30f; }
                if (c1 >= kvalid) { s[j][1] = -1e30f; s[j][3] = -1e30f; }
            }
        }

        // ---- online softmax (rows g, g+8 spread over 4 lanes) ----
        float tm0 = -1e30f, tm1 = -1e30f;
#pragma unroll
        for (int j = 0; j < 8; j++) {
            tm0 = fmaxf(tm0, fmaxf(s[j][0], s[j][1]));
            tm1 = fmaxf(tm1, fmaxf(s[j][2], s[j][3]));
        }
        tm0 = fmaxf(tm0, __shfl_xor_sync(0xffffffffu, tm0, 1));
        tm0 = fmaxf(tm0, __shfl_xor_sync(0xffffffffu, tm0, 2));
        tm1 = fmaxf(tm1, __shfl_xor_sync(0xffffffffu, tm1, 1));
        tm1 = fmaxf(tm1, __shfl_xor_sync(0xffffffffu, tm1, 2));
        float nm0 = fmaxf(mrow0, tm0), nm1 = fmaxf(mrow1, tm1);
        float corr0 = __expf(mrow0 - nm0), corr1 = __expf(mrow1 - nm1);
        float sum0 = 0.f, sum1 = 0.f;
#pragma unroll
        for (int j = 0; j < 8; j++) {
            s[j][0] = __expf(s[j][0] - nm0);
            s[j][1] = __expf(s[j][1] - nm0);
            s[j][2] = __expf(s[j][2] - nm1);
            s[j][3] = __expf(s[j][3] - nm1);
            sum0 += s[j][0] + s[j][1];
            sum1 += s[j][2] + s[j][3];
        }
        sum0 += __shfl_xor_sync(0xffffffffu, sum0, 1);
        sum0 += __shfl_xor_sync(0xffffffffu, sum0, 2);
        sum1 += __shfl_xor_sync(0xffffffffu, sum1, 1);
        sum1 += __shfl_xor_sync(0xffffffffu, sum1, 2);
        lrow0 = lrow0 * corr0 + sum0;  mrow0 = nm0;
        lrow1 = lrow1 * corr1 + sum1;  mrow1 = nm1;
#pragma unroll
        for (int nd = 0; nd < 8; nd++) {
            o[nd][0] *= corr0; o[nd][1] *= corr0;
            o[nd][2] *= corr1; o[nd][3] *= corr1;
        }

        // ---- O += P @ V : P already in A-fragment layout (no shuffles) ----
#pragma unroll
        for (int kc = 0; kc < 4; kc++) {
            uint32_t af[4];
            af[0] = packbf(s[2 * kc][0], s[2 * kc][1]);
            af[1] = packbf(s[2 * kc][2], s[2 * kc][3]);
            af[2] = packbf(s[2 * kc + 1][0], s[2 * kc + 1][1]);
            af[3] = packbf(s[2 * kc + 1][2], s[2 * kc + 1][3]);
#pragma unroll
            for (int ndp = 0; ndp < 4; ndp++) {
                int row = kc * 16 + ((lane >> 3) & 1) * 8 + (lane & 7);
                int col = ndp * 16 + (lane >> 4) * 8;
                uint32_t a = smaddr(&Vs[buf][row][col]);
                uint32_t vb0, vb1, vb2, vb3;
                LDSM4T(vb0, vb1, vb2, vb3, a);
                uint32_t bfr[2];
                bfr[0] = vb0; bfr[1] = vb1;
                mma_bf16(o[ndp * 2], af, bfr);
                bfr[0] = vb2; bfr[1] = vb3;
                mma_bf16(o[ndp * 2 + 1], af, bfr);
            }
        }
    }

    // ---- write attended rows (bf16) ----
    float inv0 = 1.0f / lrow0, inv1 = 1.0f / lrow1;
    int row0 = q0 + warp * 16 + g, row1 = row0 + 8;
    int cb = h * HD;
#pragma unroll
    for (int nd = 0; nd < 8; nd++) {
        int col = cb + nd * 8 + t * 2;
        if (row0 < SA)
            *(uint32_t*)(attout + ((size_t)b * SA + row0) * HID + col) =
                packbf(o[nd][0] * inv0, o[nd][1] * inv0);
        if (row1 < SA)
            *(uint32_t*)(attout + ((size_t)b * SA + row1) * HID + col) =
                packbf(o[nd][2] * inv1, o[nd][3] * inv1);
    }
}

// ---------------- residual + LayerNorm epilogue ------------------------------
__global__ __launch_bounds__(256) void ln_kernel(
    const float* __restrict__ aug, const float* __restrict__ proj,
    const float* __restrict__ gamma, const float* __restrict__ beta,
    float* __restrict__ out)
{
    int s = blockIdx.x, b = blockIdx.y, seq = blockIdx.z;
    int tid = threadIdx.x;
    size_t roff = (((size_t)seq * BATCH + b) * SA + s) * HID;
    int j = tid * 4;

    float4 a = *(const float4*)(aug + roff + j);
    float4 p = *(const float4*)(proj + roff + j);
    float4 x = make_float4(a.x + p.x, a.y + p.y, a.z + p.z, a.w + p.w);

    __shared__ float wsum[8];
    float lsum = x.x + x.y + x.z + x.w;
#pragma unroll
    for (int m = 16; m >= 1; m >>= 1) lsum += __shfl_xor_sync(0xffffffffu, lsum, m);
    if ((tid & 31) == 0) wsum[tid >> 5] = lsum;
    __syncthreads();
    float tot = 0.f;
#pragma unroll
    for (int w = 0; w < 8; w++) tot += wsum[w];
    float mean = tot * (1.0f / HID);

    float dx = x.x - mean, dy = x.y - mean, dz = x.z - mean, dw = x.w - mean;
    float lvar = dx * dx + dy * dy + dz * dz + dw * dw;
#pragma unroll
    for (int m = 16; m >= 1; m >>= 1) lvar += __shfl_xor_sync(0xffffffffu, lvar, m);
    __syncthreads();
    if ((tid & 31) == 0) wsum[tid >> 5] = lvar;
    __syncthreads();
    float tot2 = 0.f;
#pragma unroll
    for (int w = 0; w < 8; w++) tot2 += wsum[w];
    float rstd = rsqrtf(tot2 * (1.0f / HID) + 1e-5f);

    float4 g = *(const float4*)(gamma + j);
    float4 be = *(const float4*)(beta + j);
    float4 oo = make_float4(dx * rstd * g.x + be.x, dy * rstd * g.y + be.y,
                            dz * rstd * g.z + be.z, dw * rstd * g.w + be.w);
    size_t oidx = (size_t)seq * (2ull * SEQ * HID) + ((size_t)b * SEQ + s) * HID + j;
    *(float4*)(out + oidx) = oo;
}

// ---------------- launch ------------------------------------------------------
extern "C" void kernel_launch(void* const* d_in, const int* in_sizes, int n_in,
                              void* d_out, int out_size)
{
    const float* cnn = (const float*)d_in[0];
    const float* llm = (const float*)d_in[1];
    const float* Wq  = (const float*)d_in[2];  const float* bq = (const float*)d_in[3];
    const float* Wk  = (const float*)d_in[4];  const float* bk = (const float*)d_in[5];
    const float* Wv  = (const float*)d_in[6];  const float* bv = (const float*)d_in[7];
    const float* Wo  = (const float*)d_in[8];  const float* bo = (const float*)d_in[9];
    const float* ee  = (const float*)d_in[10];
    const float* me  = (const float*)d_in[11];
    const float* pe  = (const float*)d_in[12];
    const float* gamma = (const float*)d_in[13];
    const float* beta  = (const float*)d_in[14];

    float *aug, *proj;
    bf16 *augh, *q, *k, *v, *att, *wh;
    cudaGetSymbolAddress((void**)&aug,  g_aug);
    cudaGetSymbolAddress((void**)&augh, g_augh);
    cudaGetSymbolAddress((void**)&q,    g_q);
    cudaGetSymbolAddress((void**)&k,    g_k);
    cudaGetSymbolAddress((void**)&v,    g_v);
    cudaGetSymbolAddress((void**)&att,  g_att);
    cudaGetSymbolAddress((void**)&proj, g_proj);
    cudaGetSymbolAddress((void**)&wh,   g_wh);

    build_aug_kernel<<<dim3(SA, BATCH, 2), 256>>>(cnn, llm, ee, me, pe, aug, augh);
    conv_w_kernel<<<dim3(HID * HID / 1024, 4), 256>>>(Wq, Wk, Wv, Wo, wh);

    const int M = MROWS;                              // 8204
    dim3 gqkv((M + 127) / 128, HID / 128, 3);         // (65, 8, 3)
    gemm_bf16<1><<<gqkv, 256>>>(augh, wh, bq, bk, bv, q, k, v, M);

    dim3 ga((SA + 127) / 128, NH, 4);                 // (17, 16, 4)
    attn_bf16<<<ga, 256>>>(q, k, v, att);

    dim3 go((M + 127) / 128, HID / 128, 1);           // (65, 8)
    gemm_bf16<0><<<go, 256>>>(att, wh + (size_t)3 * HID * HID,
                              bo, bo, bo, proj, proj, proj, M);

    ln_kernel<<<dim3(SEQ, BATCH, 2), 256>>>(aug, proj, gamma, beta, (float*)d_out);
}